// round 1
// baseline (speedup 1.0000x reference)
#include <cuda_runtime.h>
#include <math.h>

#define NN   8192
#define FIN  256
#define NH   4
#define ND   64
#define HD   256

// ---------------- device scratch (allocation-free contract) ----------------
__device__ float g_h  [NN * HD];     // projected features (N, H*D)
__device__ float g_nsl[NH * NN];     // -score_l, layout [head][node]
__device__ float g_el [NH * NN];     // exp(score_l)
__device__ float g_el2[NH * NN];     // exp(0.2*score_l)
__device__ float g_sr [NH * NN];     // score_r
__device__ float g_er [NH * NN];     // exp(score_r)
__device__ float g_er2[NH * NN];     // exp(0.2*score_r)

// ---------------- packed f32x2 helpers (Blackwell FFMA2) ----------------
__device__ __forceinline__ unsigned long long pk2(float v) {
    unsigned long long r;
    asm("mov.b64 %0, {%1, %1};" : "=l"(r) : "f"(v));
    return r;
}
__device__ __forceinline__ void fma2(unsigned long long& d, unsigned long long a, unsigned long long b) {
    asm("fma.rn.f32x2 %0, %1, %2, %0;" : "+l"(d) : "l"(a), "l"(b));
}
__device__ __forceinline__ float2 unpk(unsigned long long v) {
    float2 f;
    asm("mov.b64 {%0, %1}, %2;" : "=f"(f.x), "=f"(f.y) : "l"(v));
    return f;
}

// ---------------- Kernel 1: g_h = x @ W  (8192x256 @ 256x256) ----------------
__global__ __launch_bounds__(256) void k_proj(const float* __restrict__ A,
                                              const float* __restrict__ B) {
    __shared__ float As[64 * 17];   // [m][k] padded
    __shared__ float Bs[16 * 64];   // [k][n]
    const int t  = threadIdx.x;
    const int ty = t >> 4, tx = t & 15;
    const int row0 = blockIdx.y * 64, col0 = blockIdx.x * 64;
    float acc[4][4] = {};
    for (int k0 = 0; k0 < FIN; k0 += 16) {
        #pragma unroll
        for (int l = 0; l < 4; ++l) {
            int idx = t + l * 256;
            int m = idx >> 4, k = idx & 15;
            As[m * 17 + k] = A[(size_t)(row0 + m) * FIN + k0 + k];
            int kb = idx >> 6, n = idx & 63;
            Bs[kb * 64 + n] = B[(size_t)(k0 + kb) * HD + col0 + n];
        }
        __syncthreads();
        #pragma unroll
        for (int k = 0; k < 16; ++k) {
            float a0 = As[(ty * 4 + 0) * 17 + k];
            float a1 = As[(ty * 4 + 1) * 17 + k];
            float a2 = As[(ty * 4 + 2) * 17 + k];
            float a3 = As[(ty * 4 + 3) * 17 + k];
            float4 b = *(const float4*)&Bs[k * 64 + tx * 4];
            acc[0][0] += a0 * b.x; acc[0][1] += a0 * b.y; acc[0][2] += a0 * b.z; acc[0][3] += a0 * b.w;
            acc[1][0] += a1 * b.x; acc[1][1] += a1 * b.y; acc[1][2] += a1 * b.z; acc[1][3] += a1 * b.w;
            acc[2][0] += a2 * b.x; acc[2][1] += a2 * b.y; acc[2][2] += a2 * b.z; acc[2][3] += a2 * b.w;
            acc[3][0] += a3 * b.x; acc[3][1] += a3 * b.y; acc[3][2] += a3 * b.z; acc[3][3] += a3 * b.w;
        }
        __syncthreads();
    }
    #pragma unroll
    for (int i = 0; i < 4; ++i) {
        float4 v = make_float4(acc[i][0], acc[i][1], acc[i][2], acc[i][3]);
        *(float4*)&g_h[(size_t)(row0 + ty * 4 + i) * HD + col0 + tx * 4] = v;
    }
}

// ---------------- Kernel 2: per-(node, head) scores + exp factors ----------------
__global__ __launch_bounds__(128) void k_scores(const float* __restrict__ a_l,
                                                const float* __restrict__ a_r) {
    const int n = blockIdx.x;
    const int head = threadIdx.x >> 5, lane = threadIdx.x & 31;
    const float* hr = g_h + (size_t)n * HD + head * ND;
    const float v0 = hr[lane], v1 = hr[lane + 32];
    const float* al = a_l + head * ND;
    const float* ar = a_r + head * ND;
    float sl = v0 * al[lane] + v1 * al[lane + 32];
    float sr = v0 * ar[lane] + v1 * ar[lane + 32];
    #pragma unroll
    for (int off = 16; off; off >>= 1) {
        sl += __shfl_xor_sync(0xffffffffu, sl, off);
        sr += __shfl_xor_sync(0xffffffffu, sr, off);
    }
    if (lane == 0) {
        const int idx = head * NN + n;
        g_nsl[idx] = -sl;
        g_el [idx] = expf(sl);
        g_el2[idx] = expf(0.2f * sl);
        g_sr [idx] = sr;
        g_er [idx] = expf(sr);
        g_er2[idx] = expf(0.2f * sr);
    }
}

// ---------------- Kernel 3: fused masked-softmax aggregation ----------------
// block = (64 i-rows) x (2 heads); grid = (2 head-blocks, 128 i-tiles)
// thread layout (inner): rg = tid&15 -> rows rg*4..+3 ; cg = tid>>4 -> cols cg*8..+7 of 128
#define BM 64
#define BJ 64
#define HPB 2
#define SMEM_BYTES ((8192 + 8192 + 4160 + 3 * 128 + 256) * 4)

__global__ __launch_bounds__(256, 2) void k_gat(const int* __restrict__ adj,
                                                float* __restrict__ out) {
    extern __shared__ float sm[];
    float* hT     = sm;                       // [BJ][128]
    float* wT     = sm + 8192;                // [BJ][2][64]  (w[j][h][r])
    int*   adjT   = (int*)(sm + 16384);       // [64][65] padded
    float* srT    = sm + 16384 + 4160;        // [2][64]
    float* erT    = srT + 128;                // [2][64]
    float* er2T   = erT + 128;                // [2][64]
    float* denomS = er2T + 128;               // [2][2][64] (jhalf, h, r)

    const int tid = threadIdx.x;
    const int hb  = blockIdx.x * HPB;         // head base
    const int i0  = blockIdx.y * BM;

    const int rg = tid & 15;
    const int cg = tid >> 4;
    const int hl = cg >> 3;

    // w-generation mapping: (row 0..63, local head 0..1, j-half 0..1)
    const int wr  = tid & 63;
    const int wh  = (tid >> 6) & 1;
    const int wjh = tid >> 7;

    const int gw = (hb + wh) * NN + i0 + wr;
    const float nslr = g_nsl[gw];
    const float elr  = g_el [gw];
    const float el2r = g_el2[gw];
    const int   diagj = i0 + wr;

    unsigned long long acc[4][4];
    #pragma unroll
    for (int i = 0; i < 4; ++i)
        #pragma unroll
        for (int j = 0; j < 4; ++j) acc[i][j] = 0ull;
    float dtot = 0.f;

    for (int jt = 0; jt < NN / BJ; ++jt) {
        const int j0 = jt * BJ;
        __syncthreads();
        // stage h tile: 64 j-rows x 128 cols (this block's 2 heads)
        #pragma unroll
        for (int l = 0; l < 8; ++l) {
            int f = tid + l * 256;                      // float4 index, 2048 total
            int jr = f >> 5, c4 = f & 31;
            ((float4*)hT)[f] = *(const float4*)(g_h + (size_t)(j0 + jr) * HD + hb * ND + c4 * 4);
        }
        // stage adj tile: 64 x 64 ints, padded stride 65
        #pragma unroll
        for (int l = 0; l < 4; ++l) {
            int f = tid + l * 256;                      // int4 index, 1024 total
            int r = f >> 4, c4 = f & 15;
            int4 v = *(const int4*)(adj + (size_t)(i0 + r) * NN + j0 + c4 * 4);
            int* dst = adjT + r * 65 + c4 * 4;
            dst[0] = v.x; dst[1] = v.y; dst[2] = v.z; dst[3] = v.w;
        }
        // stage per-j score factors for the 2 heads
        if (tid < 128) {
            int h2 = tid >> 6, jj = tid & 63;
            size_t gi = (size_t)(hb + h2) * NN + j0 + jj;
            srT [tid] = g_sr [gi];
            erT [tid] = g_er [gi];
            er2T[tid] = g_er2[gi];
        }
        __syncthreads();

        // weight generation: w[j][h][r] = keep ? (s>0 ? el*er : el2*er2) : 0
        {
            float ds = 0.f;
            const int jb = wjh * 32;
            #pragma unroll 8
            for (int jj = 0; jj < 32; ++jj) {
                int jc = jb + jj;
                int av = adjT[wr * 65 + jc];
                float w = 0.f;
                if (av != 0 || (j0 + jc) == diagj) {
                    float srv = srT[wh * 64 + jc];
                    w = (srv > nslr) ? (elr * erT[wh * 64 + jc])
                                     : (el2r * er2T[wh * 64 + jc]);
                }
                wT[jc * 128 + wh * 64 + wr] = w;
                ds += w;
            }
            dtot += ds;   // per-thread denominator partial (deterministic, no atomics)
        }
        __syncthreads();

        // accumulation: acc[r][*] += w[j][h][r] * h[j][cols]  (packed f32x2)
        const float* wp0 = wT + hl * 64 + rg * 4;
        const float* hp0 = hT + cg * 8;
        #pragma unroll 8
        for (int j = 0; j < BJ; ++j) {
            float4 w4 = *(const float4*)(wp0 + j * 128);
            ulonglong2 ua = *(const ulonglong2*)(hp0 + j * 128);
            ulonglong2 ub = *(const ulonglong2*)(hp0 + j * 128 + 4);
            unsigned long long w;
            w = pk2(w4.x);
            fma2(acc[0][0], w, ua.x); fma2(acc[0][1], w, ua.y);
            fma2(acc[0][2], w, ub.x); fma2(acc[0][3], w, ub.y);
            w = pk2(w4.y);
            fma2(acc[1][0], w, ua.x); fma2(acc[1][1], w, ua.y);
            fma2(acc[1][2], w, ub.x); fma2(acc[1][3], w, ub.y);
            w = pk2(w4.z);
            fma2(acc[2][0], w, ua.x); fma2(acc[2][1], w, ua.y);
            fma2(acc[2][2], w, ub.x); fma2(acc[2][3], w, ub.y);
            w = pk2(w4.w);
            fma2(acc[3][0], w, ua.x); fma2(acc[3][1], w, ua.y);
            fma2(acc[3][2], w, ub.x); fma2(acc[3][3], w, ub.y);
        }
    }

    denomS[wjh * 128 + wh * 64 + wr] = dtot;
    __syncthreads();

    // epilogue: divide by softmax denominator, store
    const int head = hb + hl;
    const int colb = (cg & 7) * 8;
    #pragma unroll
    for (int rr = 0; rr < 4; ++rr) {
        int rl = rg * 4 + rr;
        float den = denomS[hl * 64 + rl] + denomS[128 + hl * 64 + rl];
        float inv = 1.0f / den;
        float2 p0 = unpk(acc[rr][0]);
        float2 p1 = unpk(acc[rr][1]);
        float2 p2 = unpk(acc[rr][2]);
        float2 p3 = unpk(acc[rr][3]);
        float4 v0 = make_float4(p0.x * inv, p0.y * inv, p1.x * inv, p1.y * inv);
        float4 v1 = make_float4(p2.x * inv, p2.y * inv, p3.x * inv, p3.y * inv);
        float* op = out + (size_t)(i0 + rl) * HD + head * ND + colb;
        *(float4*)op       = v0;
        *(float4*)(op + 4) = v1;
    }
}

// ---------------- launch ----------------
extern "C" void kernel_launch(void* const* d_in, const int* in_sizes, int n_in,
                              void* d_out, int out_size) {
    const float* x   = (const float*)d_in[0];
    const int*   adj = (const int*)  d_in[1];
    const float* W   = (const float*)d_in[2];
    const float* a_l = (const float*)d_in[3];
    const float* a_r = (const float*)d_in[4];
    float* out = (float*)d_out;

    k_proj<<<dim3(HD / 64, NN / 64), 256>>>(x, W);
    k_scores<<<NN, 128>>>(a_l, a_r);

    cudaFuncSetAttribute(k_gat, cudaFuncAttributeMaxDynamicSharedMemorySize, SMEM_BYTES);
    k_gat<<<dim3(NH / HPB, NN / BM), 256, SMEM_BYTES>>>(adj, out);
}

// round 2
// speedup vs baseline: 2.5138x; 2.5138x over previous
#include <cuda_runtime.h>
#include <math.h>

#define NN   8192
#define FIN  256
#define NH   4
#define ND   64
#define HD   256
#define LDW  68
#define LDB  68

// ---------------- device scratch (allocation-free contract) ----------------
__device__ float g_hT [NH * ND * NN];   // projected features, transposed: [h][d][n]
__device__ float g_nsl[NH * NN];        // -score_l, layout [head][node]
__device__ float g_el [NH * NN];        // exp(score_l)
__device__ float g_el2[NH * NN];        // exp(0.2*score_l)
__device__ float g_sr [NH * NN];        // score_r
__device__ float g_er [NH * NN];        // exp(score_r)
__device__ float g_er2[NH * NN];        // exp(0.2*score_r)

// ---------------- helpers ----------------
__device__ __forceinline__ float tf32r(float x) {
    unsigned int u;
    asm("cvt.rna.tf32.f32 %0, %1;" : "=r"(u) : "f"(x));
    return __uint_as_float(u);
}
__device__ __forceinline__ void ldsm4(unsigned int* r, unsigned int addr) {
    asm volatile("ldmatrix.sync.aligned.m8n8.x4.shared.b16 {%0,%1,%2,%3}, [%4];"
                 : "=r"(r[0]), "=r"(r[1]), "=r"(r[2]), "=r"(r[3]) : "r"(addr));
}
__device__ __forceinline__ void mma_tf32(float* c, const unsigned int* a,
                                         unsigned int b0, unsigned int b1) {
    asm volatile("mma.sync.aligned.m16n8k8.row.col.f32.tf32.tf32.f32 "
                 "{%0,%1,%2,%3}, {%4,%5,%6,%7}, {%8,%9}, {%0,%1,%2,%3};"
                 : "+f"(c[0]), "+f"(c[1]), "+f"(c[2]), "+f"(c[3])
                 : "r"(a[0]), "r"(a[1]), "r"(a[2]), "r"(a[3]), "r"(b0), "r"(b1));
}

// ---------------- Kernel 1: g_hT[h][d][n] = (x @ W)^T ----------------
__global__ __launch_bounds__(256) void k_proj(const float* __restrict__ A,
                                              const float* __restrict__ B) {
    __shared__ float As[64 * 17];    // [m][k] padded
    __shared__ float Bs[16 * 64];    // [k][n]
    __shared__ float Tb[64 * 68];    // transpose buffer [col][row]
    const int t  = threadIdx.x;
    const int ty = t >> 4, tx = t & 15;
    const int row0 = blockIdx.y * 64, col0 = blockIdx.x * 64;
    float acc[4][4] = {};
    for (int k0 = 0; k0 < FIN; k0 += 16) {
        #pragma unroll
        for (int l = 0; l < 4; ++l) {
            int idx = t + l * 256;
            int m = idx >> 4, k = idx & 15;
            As[m * 17 + k] = A[(size_t)(row0 + m) * FIN + k0 + k];
            int kb = idx >> 6, n = idx & 63;
            Bs[kb * 64 + n] = B[(size_t)(k0 + kb) * HD + col0 + n];
        }
        __syncthreads();
        #pragma unroll
        for (int k = 0; k < 16; ++k) {
            float a0 = As[(ty * 4 + 0) * 17 + k];
            float a1 = As[(ty * 4 + 1) * 17 + k];
            float a2 = As[(ty * 4 + 2) * 17 + k];
            float a3 = As[(ty * 4 + 3) * 17 + k];
            float4 b = *(const float4*)&Bs[k * 64 + tx * 4];
            acc[0][0] += a0 * b.x; acc[0][1] += a0 * b.y; acc[0][2] += a0 * b.z; acc[0][3] += a0 * b.w;
            acc[1][0] += a1 * b.x; acc[1][1] += a1 * b.y; acc[1][2] += a1 * b.z; acc[1][3] += a1 * b.w;
            acc[2][0] += a2 * b.x; acc[2][1] += a2 * b.y; acc[2][2] += a2 * b.z; acc[2][3] += a2 * b.w;
            acc[3][0] += a3 * b.x; acc[3][1] += a3 * b.y; acc[3][2] += a3 * b.z; acc[3][3] += a3 * b.w;
        }
        __syncthreads();
    }
    // transpose through smem, then coalesced stores to g_hT[col][row]
    #pragma unroll
    for (int i = 0; i < 4; ++i)
        #pragma unroll
        for (int j = 0; j < 4; ++j)
            Tb[(tx * 4 + j) * 68 + (ty * 4 + i)] = acc[i][j];
    __syncthreads();
    const int c = t >> 2, q = t & 3;
    #pragma unroll
    for (int m = 0; m < 4; ++m) {
        float4 v = *(const float4*)&Tb[c * 68 + q * 16 + m * 4];
        *(float4*)(g_hT + (size_t)(col0 + c) * NN + row0 + q * 16 + m * 4) = v;
    }
}

// ---------------- Kernel 2: per-(node, head) scores + exp factors ----------------
__global__ __launch_bounds__(256) void k_scores(const float* __restrict__ a_l,
                                                const float* __restrict__ a_r) {
    __shared__ float alS[HD], arS[HD];
    const int t = threadIdx.x;
    if (t < HD) { alS[t] = a_l[t]; arS[t] = a_r[t]; }
    __syncthreads();
    const int n = blockIdx.x * 256 + t;
    #pragma unroll
    for (int h = 0; h < NH; ++h) {
        float sl = 0.f, sr = 0.f;
        #pragma unroll 8
        for (int d = 0; d < ND; ++d) {
            float v = g_hT[(size_t)(h * ND + d) * NN + n];
            sl += v * alS[h * ND + d];
            sr += v * arS[h * ND + d];
        }
        const int idx = h * NN + n;
        g_nsl[idx] = -sl;
        g_el [idx] = expf(sl);
        g_el2[idx] = expf(0.2f * sl);
        g_sr [idx] = sr;
        g_er [idx] = expf(sr);
        g_er2[idx] = expf(0.2f * sr);
    }
}

// ---------------- Kernel 3: fused masked-softmax aggregation via tf32 HMMA ----------------
// block: 128 i-rows x 1 head (full 64 d-cols). 256 threads = 8 warps (4 M x 2 N).
// K loop over j in chunks of 64; attention weights generated into smem as tf32.
#define SMEM_FLOATS (128*LDW + 64*LDB + 3*128 + 128*17 + 128)
#define SMEM_BYTES  (SMEM_FLOATS * 4)

__global__ __launch_bounds__(256, 2) void k_gat(const int* __restrict__ adj,
                                                float* __restrict__ out) {
    extern __shared__ float sm[];
    float* wS     = sm;                          // [128][LDW] attention weights (tf32 bits)
    float* BtS    = sm + 128 * LDW;              // [64 n][LDB] h features (tf32 bits)
    float* nslS   = sm + 128 * LDW + 64 * LDB;   // [128]
    float* elS    = nslS + 128;                  // [128]
    float* el2S   = elS + 128;                   // [128]
    float* denomP = el2S + 128;                  // [128][17]
    float* invD   = denomP + 128 * 17;           // [128]

    const int tid  = threadIdx.x;
    const int lane = tid & 31;
    const int warp = tid >> 5;
    const int h    = blockIdx.x;
    const int i0   = blockIdx.y * 128;

    // block-static staging of i-row factors
    if (tid < 128) {
        nslS[tid] = g_nsl[h * NN + i0 + tid];
        elS [tid] = g_el [h * NN + i0 + tid];
        el2S[tid] = g_el2[h * NN + i0 + tid];
    }

    // weight-gen mapping: lanes along j (coalesced adj)
    const int ii  = tid >> 4;       // 0..15 (base i row)
    const int jj4 = tid & 15;       // 0..15 (j quad)

    // B staging mapping
    const int bn = tid >> 2;        // 0..63 (feature)
    const int bq = tid & 3;         // 0..3
    const float* hTrow = g_hT + (size_t)(h * ND + bn) * NN;

    // mma mapping
    const int wm = warp >> 1;       // 0..3
    const int wn = warp & 1;        // 0..1
    unsigned int sbase = (unsigned int)__cvta_generic_to_shared(sm);
    unsigned int aAddr0 = sbase + ((wm * 32 + (lane & 15)) * LDW + (lane >> 4) * 4) * 4;
    unsigned int aAddr1 = aAddr0 + 16 * LDW * 4;
    unsigned int bAddr[4];
    #pragma unroll
    for (int nt = 0; nt < 4; ++nt)
        bAddr[nt] = sbase + 128 * LDW * 4 +
                    ((wn * 32 + nt * 8 + (lane & 7)) * LDB + (lane >> 3) * 4) * 4;

    float acc[2][4][4];
    #pragma unroll
    for (int a = 0; a < 2; ++a)
        #pragma unroll
        for (int b = 0; b < 4; ++b)
            #pragma unroll
            for (int c = 0; c < 4; ++c) acc[a][b][c] = 0.f;
    float dpart[8] = {};

    const float* srG  = g_sr  + h * NN;
    const float* erG  = g_er  + h * NN;
    const float* er2G = g_er2 + h * NN;

    for (int jt = 0; jt < NN / 64; ++jt) {
        const int j0 = jt * 64;
        __syncthreads();   // protect wS/BtS from previous chunk's mma reads

        // ---- stage B tile (h features, tf32-rounded) ----
        #pragma unroll
        for (int m = 0; m < 4; ++m) {
            float4 v = *(const float4*)(hTrow + j0 + bq * 16 + m * 4);
            v.x = tf32r(v.x); v.y = tf32r(v.y); v.z = tf32r(v.z); v.w = tf32r(v.w);
            *(float4*)&BtS[bn * LDB + bq * 16 + m * 4] = v;
        }

        // ---- generate attention-weight tile (tf32-rounded) ----
        const float4 sr4  = *(const float4*)(srG  + j0 + jj4 * 4);
        const float4 er4  = *(const float4*)(erG  + j0 + jj4 * 4);
        const float4 er24 = *(const float4*)(er2G + j0 + jj4 * 4);
        const int jb = j0 + jj4 * 4;
        #pragma unroll
        for (int k = 0; k < 8; ++k) {
            const int i  = k * 16 + ii;
            const int gi = i0 + i;
            const int4 av = *(const int4*)(adj + (size_t)gi * NN + j0 + jj4 * 4);
            const float nsl_i = nslS[i], el_i = elS[i], el2_i = el2S[i];
            float w0 = (av.x | (gi == jb + 0)) ? ((sr4.x > nsl_i) ? el_i * er4.x : el2_i * er24.x) : 0.f;
            float w1 = (av.y | (gi == jb + 1)) ? ((sr4.y > nsl_i) ? el_i * er4.y : el2_i * er24.y) : 0.f;
            float w2 = (av.z | (gi == jb + 2)) ? ((sr4.z > nsl_i) ? el_i * er4.z : el2_i * er24.z) : 0.f;
            float w3 = (av.w | (gi == jb + 3)) ? ((sr4.w > nsl_i) ? el_i * er4.w : el2_i * er24.w) : 0.f;
            w0 = tf32r(w0); w1 = tf32r(w1); w2 = tf32r(w2); w3 = tf32r(w3);
            dpart[k] += (w0 + w1) + (w2 + w3);
            *(float4*)&wS[i * LDW + jj4 * 4] = make_float4(w0, w1, w2, w3);
        }
        __syncthreads();

        // ---- tensor-core accumulation ----
        #pragma unroll
        for (int kp = 0; kp < 4; ++kp) {
            unsigned int bf[4][4];
            #pragma unroll
            for (int nt = 0; nt < 4; ++nt) ldsm4(bf[nt], bAddr[nt] + kp * 64);
            #pragma unroll
            for (int sub = 0; sub < 2; ++sub) {
                const int ks = kp * 2 + sub;
                unsigned int a0[4], a1[4];
                ldsm4(a0, aAddr0 + ks * 32);
                ldsm4(a1, aAddr1 + ks * 32);
                #pragma unroll
                for (int nt = 0; nt < 4; ++nt) {
                    mma_tf32(acc[0][nt], a0, bf[nt][2 * sub], bf[nt][2 * sub + 1]);
                    mma_tf32(acc[1][nt], a1, bf[nt][2 * sub], bf[nt][2 * sub + 1]);
                }
            }
        }
    }

    // ---- softmax denominators (deterministic tree) ----
    #pragma unroll
    for (int k = 0; k < 8; ++k)
        denomP[(k * 16 + ii) * 17 + jj4] = dpart[k];
    __syncthreads();
    if (tid < 128) {
        float s = 0.f;
        #pragma unroll
        for (int q = 0; q < 16; ++q) s += denomP[tid * 17 + q];
        invD[tid] = 1.0f / s;
    }
    __syncthreads();

    // ---- epilogue: normalize + store ----
    #pragma unroll
    for (int mt = 0; mt < 2; ++mt) {
        const int r0 = wm * 32 + mt * 16 + (lane >> 2);
        const float inv0 = invD[r0], inv1 = invD[r0 + 8];
        #pragma unroll
        for (int nt = 0; nt < 4; ++nt) {
            const int c = h * ND + wn * 32 + nt * 8 + (lane & 3) * 2;
            float2 v0 = make_float2(acc[mt][nt][0] * inv0, acc[mt][nt][1] * inv0);
            float2 v1 = make_float2(acc[mt][nt][2] * inv1, acc[mt][nt][3] * inv1);
            *(float2*)(out + (size_t)(i0 + r0)     * HD + c) = v0;
            *(float2*)(out + (size_t)(i0 + r0 + 8) * HD + c) = v1;
        }
    }
}

// ---------------- launch ----------------
extern "C" void kernel_launch(void* const* d_in, const int* in_sizes, int n_in,
                              void* d_out, int out_size) {
    const float* x   = (const float*)d_in[0];
    const int*   adj = (const int*)  d_in[1];
    const float* W   = (const float*)d_in[2];
    const float* a_l = (const float*)d_in[3];
    const float* a_r = (const float*)d_in[4];
    float* out = (float*)d_out;

    k_proj<<<dim3(HD / 64, NN / 64), 256>>>(x, W);
    k_scores<<<NN / 256, 256>>>(a_l, a_r);

    cudaFuncSetAttribute(k_gat, cudaFuncAttributeMaxDynamicSharedMemorySize, SMEM_BYTES);
    k_gat<<<dim3(NH, NN / 128), 256, SMEM_BYTES>>>(adj, out);
}

// round 4
// speedup vs baseline: 3.7185x; 1.4792x over previous
#include <cuda_runtime.h>
#include <math.h>
#include <stdint.h>

#define NN   8192
#define FIN  256
#define NH   4
#define ND   64
#define HD   256
#define LDW  68
#define LDB  68

// ---------------- device scratch (allocation-free contract) ----------------
__device__ float g_hT [NH * ND * NN];   // projected features, exact: [h][d][n]
__device__ float g_hB [NH * ND * NN];   // projected features, tf32-rounded: [h][d][n]
__device__ float g_nsl[NH * NN];
__device__ float g_el [NH * NN];
__device__ float g_el2[NH * NN];
__device__ float g_sr [NH * NN];
__device__ float g_er [NH * NN];
__device__ float g_er2[NH * NN];

// ---------------- helpers ----------------
__device__ __forceinline__ float tf32r(float x) {
    unsigned int u;
    asm("cvt.rna.tf32.f32 %0, %1;" : "=r"(u) : "f"(x));
    return __uint_as_float(u);
}
__device__ __forceinline__ void ldsm4(unsigned int* r, unsigned int addr) {
    asm volatile("ldmatrix.sync.aligned.m8n8.x4.shared.b16 {%0,%1,%2,%3}, [%4];"
                 : "=r"(r[0]), "=r"(r[1]), "=r"(r[2]), "=r"(r[3]) : "r"(addr));
}
__device__ __forceinline__ void mma_tf32(float* c, const unsigned int* a,
                                         unsigned int b0, unsigned int b1) {
    asm volatile("mma.sync.aligned.m16n8k8.row.col.f32.tf32.tf32.f32 "
                 "{%0,%1,%2,%3}, {%4,%5,%6,%7}, {%8,%9}, {%0,%1,%2,%3};"
                 : "+f"(c[0]), "+f"(c[1]), "+f"(c[2]), "+f"(c[3])
                 : "r"(a[0]), "r"(a[1]), "r"(a[2]), "r"(a[3]), "r"(b0), "r"(b1));
}

// ---------------- Kernel 1: g_hT/g_hB = (x @ W)^T ----------------
__global__ __launch_bounds__(256) void k_proj(const float* __restrict__ A,
                                              const float* __restrict__ B) {
    __shared__ float As[64 * 17];
    __shared__ float Bs[16 * 64];
    __shared__ float Tb[64 * 68];
    const int t  = threadIdx.x;
    const int ty = t >> 4, tx = t & 15;
    const int row0 = blockIdx.y * 64, col0 = blockIdx.x * 64;
    float acc[4][4] = {};
    for (int k0 = 0; k0 < FIN; k0 += 16) {
        #pragma unroll
        for (int l = 0; l < 4; ++l) {
            int idx = t + l * 256;
            int m = idx >> 4, k = idx & 15;
            As[m * 17 + k] = A[(size_t)(row0 + m) * FIN + k0 + k];
            int kb = idx >> 6, n = idx & 63;
            Bs[kb * 64 + n] = B[(size_t)(k0 + kb) * HD + col0 + n];
        }
        __syncthreads();
        #pragma unroll
        for (int k = 0; k < 16; ++k) {
            float a0 = As[(ty * 4 + 0) * 17 + k];
            float a1 = As[(ty * 4 + 1) * 17 + k];
            float a2 = As[(ty * 4 + 2) * 17 + k];
            float a3 = As[(ty * 4 + 3) * 17 + k];
            float4 b = *(const float4*)&Bs[k * 64 + tx * 4];
            acc[0][0] += a0 * b.x; acc[0][1] += a0 * b.y; acc[0][2] += a0 * b.z; acc[0][3] += a0 * b.w;
            acc[1][0] += a1 * b.x; acc[1][1] += a1 * b.y; acc[1][2] += a1 * b.z; acc[1][3] += a1 * b.w;
            acc[2][0] += a2 * b.x; acc[2][1] += a2 * b.y; acc[2][2] += a2 * b.z; acc[2][3] += a2 * b.w;
            acc[3][0] += a3 * b.x; acc[3][1] += a3 * b.y; acc[3][2] += a3 * b.z; acc[3][3] += a3 * b.w;
        }
        __syncthreads();
    }
    #pragma unroll
    for (int i = 0; i < 4; ++i)
        #pragma unroll
        for (int j = 0; j < 4; ++j)
            Tb[(tx * 4 + j) * 68 + (ty * 4 + i)] = acc[i][j];
    __syncthreads();
    const int c = t >> 2, q = t & 3;
    #pragma unroll
    for (int m = 0; m < 4; ++m) {
        float4 v = *(const float4*)&Tb[c * 68 + q * 16 + m * 4];
        size_t go = (size_t)(col0 + c) * NN + row0 + q * 16 + m * 4;
        *(float4*)(g_hT + go) = v;
        float4 r = make_float4(tf32r(v.x), tf32r(v.y), tf32r(v.z), tf32r(v.w));
        *(float4*)(g_hB + go) = r;
    }
}

// ---------------- Kernel 2: per-(node, head) scores + exp factors ----------------
__global__ __launch_bounds__(256) void k_scores(const float* __restrict__ a_l,
                                                const float* __restrict__ a_r) {
    __shared__ float alS[HD], arS[HD];
    const int t = threadIdx.x;
    if (t < HD) { alS[t] = a_l[t]; arS[t] = a_r[t]; }
    __syncthreads();
    const int n = blockIdx.x * 256 + t;
    #pragma unroll
    for (int h = 0; h < NH; ++h) {
        float sl = 0.f, sr = 0.f;
        #pragma unroll 8
        for (int d = 0; d < ND; ++d) {
            float v = g_hT[(size_t)(h * ND + d) * NN + n];
            sl += v * alS[h * ND + d];
            sr += v * arS[h * ND + d];
        }
        const int idx = h * NN + n;
        g_nsl[idx] = -sl;
        g_el [idx] = expf(sl);
        g_el2[idx] = expf(0.2f * sl);
        g_sr [idx] = sr;
        g_er [idx] = expf(sr);
        g_er2[idx] = expf(0.2f * sr);
    }
}

// ---------------- Kernel 3: fused aggregation via tf32 mma.sync, double-buffered ----
// block: 128 i-rows x 1 head. 256 threads = 8 warps (4M x 2N). One barrier per chunk.
// smem layout (floats):
//   wS : 2 x [128][LDW]      at 0         (buf stride 128*LDW = 8704)
//   BtS: 2 x [64][LDB]       at 17408     (buf stride 64*LDB = 4352)
//   denS: [128]              at 26112
//   invD: [128]              at 26240
#define WBUF   (128 * LDW)
#define BBUF   (64 * LDB)
#define OFF_BT (2 * WBUF)
#define OFF_DN (OFF_BT + 2 * BBUF)
#define OFF_IV (OFF_DN + 128)
#define SMEM_FLOATS (OFF_IV + 128)
#define SMEM_BYTES  (SMEM_FLOATS * 4)

__global__ __launch_bounds__(256, 2) void k_gat(const int* __restrict__ adj,
                                                float* __restrict__ out) {
    extern __shared__ float sm[];
    float* denS = sm + OFF_DN;
    float* invD = sm + OFF_IV;

    const int tid  = threadIdx.x;
    const int lane = tid & 31;
    const int warp = tid >> 5;
    const int h    = blockIdx.x;
    const int i0   = blockIdx.y * 128;

    // weight-gen mapping: 16 consecutive threads (jj4) cover one row-group ii
    const int ii  = tid >> 4;       // 0..15
    const int jj4 = tid & 15;       // 0..15

    // per-thread row factors for rows { k*16+ii }, hoisted for the whole block
    float nslR[8], elR[8], el2R[8];
    #pragma unroll
    for (int k = 0; k < 8; ++k) {
        const int gi = h * NN + i0 + k * 16 + ii;
        nslR[k] = g_nsl[gi];
        elR [k] = g_el [gi];
        el2R[k] = g_el2[gi];
    }

    // B staging mapping
    const int bn = tid >> 2;        // 0..63 (feature d)
    const int bq = tid & 3;         // 0..3
    const float* hp = g_hB + (size_t)(h * ND + bn) * NN;

    // mma mapping (identical to verified R2 layout, plus buffer offsets)
    const int wm = warp >> 1;
    const int wn = warp & 1;
    unsigned int sbase = (unsigned int)__cvta_generic_to_shared(sm);
    const unsigned int aAddr0 = sbase + ((wm * 32 + (lane & 15)) * LDW + (lane >> 4) * 4) * 4;
    const unsigned int aAddr1 = aAddr0 + 16 * LDW * 4;
    unsigned int bAddr[4];
    #pragma unroll
    for (int nt = 0; nt < 4; ++nt)
        bAddr[nt] = sbase + OFF_BT * 4 +
                    ((wn * 32 + nt * 8 + (lane & 7)) * LDB + (lane >> 3) * 4) * 4;

    float acc[2][4][4];
    #pragma unroll
    for (int a = 0; a < 2; ++a)
        #pragma unroll
        for (int b = 0; b < 4; ++b)
            #pragma unroll
            for (int c = 0; c < 4; ++c) acc[a][b][c] = 0.f;
    float dpart[8] = {};

    const float* srG  = g_sr  + h * NN;
    const float* erG  = g_er  + h * NN;
    const float* er2G = g_er2 + h * NN;
    const int* adjR = adj + (size_t)(i0 + ii) * NN + jj4 * 4;   // row base for k=0

    // prologue: prefetch adj chunk 0
    int4 adjp[8];
    #pragma unroll
    for (int k = 0; k < 8; ++k)
        adjp[k] = *(const int4*)(adjR + (size_t)(k * 16) * NN);

    for (int jt = 0; jt < NN / 64; ++jt) {
        const int j0  = jt * 64;
        const int buf = jt & 1;

        // ---- stage B tile (pre-rounded tf32) ----
        {
            float* bufB = sm + OFF_BT + buf * BBUF + bn * LDB + bq * 16;
            const float* hrow = hp + j0 + bq * 16;
            #pragma unroll
            for (int m = 0; m < 4; ++m)
                *(float4*)(bufB + m * 4) = *(const float4*)(hrow + m * 4);
        }

        // ---- generate attention-weight tile from prefetched adj ----
        {
            float* bufW = sm + buf * WBUF + jj4 * 4;
            const float4 sr4  = *(const float4*)(srG  + j0 + jj4 * 4);
            const float4 er4  = *(const float4*)(erG  + j0 + jj4 * 4);
            const float4 er24 = *(const float4*)(er2G + j0 + jj4 * 4);
            const int jb = j0 + jj4 * 4;
            #pragma unroll
            for (int k = 0; k < 8; ++k) {
                const int gi = i0 + k * 16 + ii;
                const int4 av = adjp[k];
                const float nsl_i = nslR[k], el_i = elR[k], el2_i = el2R[k];
                float w0 = (av.x | (gi == jb + 0)) ? ((sr4.x > nsl_i) ? el_i * er4.x : el2_i * er24.x) : 0.f;
                float w1 = (av.y | (gi == jb + 1)) ? ((sr4.y > nsl_i) ? el_i * er4.y : el2_i * er24.y) : 0.f;
                float w2 = (av.z | (gi == jb + 2)) ? ((sr4.z > nsl_i) ? el_i * er4.z : el2_i * er24.z) : 0.f;
                float w3 = (av.w | (gi == jb + 3)) ? ((sr4.w > nsl_i) ? el_i * er4.w : el2_i * er24.w) : 0.f;
                w0 = tf32r(w0); w1 = tf32r(w1); w2 = tf32r(w2); w3 = tf32r(w3);
                dpart[k] += (w0 + w1) + (w2 + w3);
                *(float4*)(bufW + (k * 16 + ii) * LDW) = make_float4(w0, w1, w2, w3);
            }
        }

        __syncthreads();   // single barrier per chunk (double-buffered)

        // ---- prefetch next chunk's adj (hides DRAM latency behind the mma block) ----
        if (jt + 1 < NN / 64) {
            #pragma unroll
            for (int k = 0; k < 8; ++k)
                adjp[k] = *(const int4*)(adjR + (size_t)(k * 16) * NN + j0 + 64);
        }

        // ---- tensor-core accumulation on this buffer ----
        const unsigned int aO = buf ? (unsigned int)(WBUF * 4) : 0u;
        const unsigned int bO = buf ? (unsigned int)(BBUF * 4) : 0u;
        #pragma unroll
        for (int kp = 0; kp < 4; ++kp) {
            unsigned int bf[4][4];
            #pragma unroll
            for (int nt = 0; nt < 4; ++nt) ldsm4(bf[nt], bAddr[nt] + bO + kp * 64);
            #pragma unroll
            for (int sub = 0; sub < 2; ++sub) {
                const int ks = kp * 2 + sub;
                unsigned int a0[4], a1[4];
                ldsm4(a0, aAddr0 + aO + ks * 32);
                ldsm4(a1, aAddr1 + aO + ks * 32);
                #pragma unroll
                for (int nt = 0; nt < 4; ++nt) {
                    mma_tf32(acc[0][nt], a0, bf[nt][2 * sub], bf[nt][2 * sub + 1]);
                    mma_tf32(acc[1][nt], a1, bf[nt][2 * sub], bf[nt][2 * sub + 1]);
                }
            }
        }
    }

    // ---- denominators: 16-lane shuffle reduction (threads for one row are contiguous) ----
    #pragma unroll
    for (int k = 0; k < 8; ++k) {
        float v = dpart[k];
        v += __shfl_xor_sync(0xffffffffu, v, 1);
        v += __shfl_xor_sync(0xffffffffu, v, 2);
        v += __shfl_xor_sync(0xffffffffu, v, 4);
        v += __shfl_xor_sync(0xffffffffu, v, 8);
        if (jj4 == 0) denS[k * 16 + ii] = v;
    }
    __syncthreads();
    if (tid < 128) invD[tid] = 1.0f / denS[tid];
    __syncthreads();

    // ---- epilogue: normalize + store ----
    #pragma unroll
    for (int mt = 0; mt < 2; ++mt) {
        const int r0 = wm * 32 + mt * 16 + (lane >> 2);
        const float inv0 = invD[r0], inv1 = invD[r0 + 8];
        #pragma unroll
        for (int nt = 0; nt < 4; ++nt) {
            const int c = h * ND + wn * 32 + nt * 8 + (lane & 3) * 2;
            float2 v0 = make_float2(acc[mt][nt][0] * inv0, acc[mt][nt][1] * inv0);
            float2 v1 = make_float2(acc[mt][nt][2] * inv1, acc[mt][nt][3] * inv1);
            *(float2*)(out + (size_t)(i0 + r0)     * HD + c) = v0;
            *(float2*)(out + (size_t)(i0 + r0 + 8) * HD + c) = v1;
        }
    }
}

// ---------------- launch ----------------
extern "C" void kernel_launch(void* const* d_in, const int* in_sizes, int n_in,
                              void* d_out, int out_size) {
    const float* x   = (const float*)d_in[0];
    const int*   adj = (const int*)  d_in[1];
    const float* W   = (const float*)d_in[2];
    const float* a_l = (const float*)d_in[3];
    const float* a_r = (const float*)d_in[4];
    float* out = (float*)d_out;

    k_proj<<<dim3(HD / 64, NN / 64), 256>>>(x, W);
    k_scores<<<NN / 256, 256>>>(a_l, a_r);

    cudaFuncSetAttribute(k_gat, cudaFuncAttributeMaxDynamicSharedMemorySize, SMEM_BYTES);
    k_gat<<<dim3(NH, NN / 128), 256, SMEM_BYTES>>>(adj, out);
}